// round 5
// baseline (speedup 1.0000x reference)
#include <cuda_runtime.h>
#include <math.h>

#define H 4096
#define INV_SQRT_D (1.0f / 64.0f)
#define NROWS (4 * H + 2)

// ---------------- device scratch (allocation-free) ----------------
__device__ float g_q[H];
__device__ float g_k[H];     // already scaled by 1/sqrt(d)
__device__ float g_v[H];
__device__ float g_opre[H];  // Wo@x + bo (pre-sigmoid)
__device__ float g_dots[2];  // wi.x, wf.x

// ---------------- reductions ----------------
__device__ __forceinline__ float warp_reduce(float v) {
    #pragma unroll
    for (int o = 16; o > 0; o >>= 1)
        v += __shfl_down_sync(0xffffffffu, v, o);
    return v;
}

// block reduce for 256 threads; result broadcast to all threads via smem.
// Caller must ensure no pending use of `buf` (we sync internally).
__device__ __forceinline__ float block_reduce_bcast_256(float v, float* buf) {
    int lane = threadIdx.x & 31;
    int wid  = threadIdx.x >> 5;
    v = warp_reduce(v);
    if (lane == 0) buf[wid] = v;
    __syncthreads();
    if (wid == 0) {
        float t = (lane < 8) ? buf[lane] : 0.0f;
        t = warp_reduce(t);
        if (lane == 0) buf[0] = t;
    }
    __syncthreads();
    return buf[0];
}

// ---------------- kernel A: all matvecs + scalar-gate dots ----------------
// One WARP per output row. 512-thread blocks (16 warps). No barriers.
__global__ void __launch_bounds__(512)
matvec_kernel(const float* __restrict__ x,
              const float* __restrict__ Wq, const float* __restrict__ Wk,
              const float* __restrict__ Wv, const float* __restrict__ Wo,
              const float* __restrict__ bq, const float* __restrict__ bk,
              const float* __restrict__ bv, const float* __restrict__ bo,
              const float* __restrict__ wi, const float* __restrict__ wf) {
    int gw   = (blockIdx.x * 512 + threadIdx.x) >> 5;  // global warp id = row
    int lane = threadIdx.x & 31;
    if (gw >= NROWS) return;

    const float* wrow;
    if      (gw <     H) wrow = Wq + (size_t) gw          * H;
    else if (gw < 2 * H) wrow = Wk + (size_t)(gw -   H)   * H;
    else if (gw < 3 * H) wrow = Wv + (size_t)(gw - 2*H)   * H;
    else if (gw < 4 * H) wrow = Wo + (size_t)(gw - 3*H)   * H;
    else                 wrow = (gw == 4 * H) ? wi : wf;

    const float4* w4 = (const float4*)wrow;
    const float4* x4 = (const float4*)x;

    float s0 = 0.0f, s1 = 0.0f;
    #pragma unroll 8
    for (int i = 0; i < (H / 4) / 32; i += 2) {   // 32 f4 per lane
        int ia = lane + i * 32;
        int ib = lane + (i + 1) * 32;
        float4 wa = __ldcs(&w4[ia]);
        float4 wb = __ldcs(&w4[ib]);
        float4 xa = x4[ia];
        float4 xb = x4[ib];
        s0 += wa.x * xa.x + wa.y * xa.y + wa.z * xa.z + wa.w * xa.w;
        s1 += wb.x * xb.x + wb.y * xb.y + wb.z * xb.z + wb.w * xb.w;
    }
    float sum = warp_reduce(s0 + s1);

    if (lane == 0) {
        if      (gw <     H) g_q[gw]          = sum + bq[gw];
        else if (gw < 2 * H) g_k[gw -   H]    = (sum + bk[gw - H]) * INV_SQRT_D;
        else if (gw < 3 * H) g_v[gw - 2*H]    = sum + bv[gw - 2*H];
        else if (gw < 4 * H) g_opre[gw - 3*H] = sum + bo[gw - 3*H];
        else                 g_dots[gw - 4*H] = sum;
    }
}

// ---------------- kernel B: fused gates + n + denom + C update + readout ----
// One 256-thread BLOCK per C row. Every block redundantly computes the gate
// scalars and denom from L2-hot vectors (cheap, fully parallel); block 0 also
// writes out_n. k,q staged to smem during the (mandatory) denom pass.
__global__ void __launch_bounds__(256)
update_kernel(const float* __restrict__ C_prev,
              const float* __restrict__ n_prev,
              const float* __restrict__ bi, const float* __restrict__ bf,
              float* __restrict__ out_h, float* __restrict__ out_C,
              float* __restrict__ out_n) {
    __shared__ float4 sk[H / 4];   // 16 KB
    __shared__ float4 sq[H / 4];   // 16 KB
    __shared__ float red[8];

    int row = blockIdx.x;
    int tid = threadIdx.x;

    // gate scalars (uniform across threads; 2-float load from g_dots)
    float ig = expf(g_dots[0] + bi[0]);
    float fg = 1.0f / (1.0f + expf(-(g_dots[1] + bf[0])));

    // denom pass: n = fg*n_prev + ig*k ; dot(n, q). Stages k,q to smem.
    const float4* k4  = (const float4*)g_k;
    const float4* q4  = (const float4*)g_q;
    const float4* np4 = (const float4*)n_prev;
    float4*       on4 = (float4*)out_n;

    float ndot = 0.0f;
    #pragma unroll
    for (int i = 0; i < (H / 4) / 256; i++) {   // 4 iters
        int idx = tid + i * 256;
        float4 kk = k4[idx];
        float4 qq = q4[idx];
        float4 np = np4[idx];
        sk[idx] = kk;
        sq[idx] = qq;
        float4 nn;
        nn.x = fg * np.x + ig * kk.x;
        nn.y = fg * np.y + ig * kk.y;
        nn.z = fg * np.z + ig * kk.z;
        nn.w = fg * np.w + ig * kk.w;
        if (row == 0) on4[idx] = nn;
        ndot += nn.x * qq.x + nn.y * qq.y + nn.z * qq.z + nn.w * qq.w;
    }
    ndot = block_reduce_bcast_256(ndot, red);   // syncs; smem staging visible after
    float invden = 1.0f / fmaxf(fabsf(ndot), 1.0f);

    // main pass: stream C_prev -> C, fused dot with q
    float ivr = ig * g_v[row];
    const float4* cp4 = (const float4*)(C_prev + (size_t)row * H);
    float4*       co4 = (float4*)      (out_C  + (size_t)row * H);

    float dot = 0.0f;
    #pragma unroll
    for (int i = 0; i < (H / 4) / 256; i++) {   // 4 iters
        int idx = tid + i * 256;
        float4 c  = __ldcs(&cp4[idx]);
        float4 kk = sk[idx];
        float4 cn;
        cn.x = fg * c.x + ivr * kk.x;
        cn.y = fg * c.y + ivr * kk.y;
        cn.z = fg * c.z + ivr * kk.z;
        cn.w = fg * c.w + ivr * kk.w;
        __stcs(&co4[idx], cn);
        float4 qq = sq[idx];
        dot += cn.x * qq.x + cn.y * qq.y + cn.z * qq.z + cn.w * qq.w;
    }
    dot = block_reduce_bcast_256(dot, red);
    if (tid == 0) {
        float h_tilde = dot * invden;
        float o = 1.0f / (1.0f + expf(-g_opre[row]));
        out_h[row] = o * h_tilde;
    }
}

// ---------------- launcher ----------------
extern "C" void kernel_launch(void* const* d_in, const int* in_sizes, int n_in,
                              void* d_out, int out_size) {
    const float* x      = (const float*)d_in[0];
    // d_in[1] = h_prev (unused by mLSTM math)
    const float* C_prev = (const float*)d_in[2];
    const float* n_prev = (const float*)d_in[3];
    const float* Wq     = (const float*)d_in[4];
    const float* Wk     = (const float*)d_in[5];
    const float* Wv     = (const float*)d_in[6];
    const float* Wo     = (const float*)d_in[7];
    const float* bq     = (const float*)d_in[8];
    const float* bk     = (const float*)d_in[9];
    const float* bv     = (const float*)d_in[10];
    const float* bo     = (const float*)d_in[11];
    const float* wi     = (const float*)d_in[12];
    const float* bi     = (const float*)d_in[13];
    const float* wf     = (const float*)d_in[14];
    const float* bf     = (const float*)d_in[15];

    float* out   = (float*)d_out;
    float* out_h = out;                      // [H]
    float* out_C = out + H;                  // [H, H]
    float* out_n = out + H + (size_t)H * H;  // [H]

    int mv_blocks = (NROWS + 15) / 16;       // 16 warp-rows per 512-thread block
    matvec_kernel<<<mv_blocks, 512>>>(x, Wq, Wk, Wv, Wo, bq, bk, bv, bo, wi, wf);
    update_kernel<<<H, 256>>>(C_prev, n_prev, bi, bf, out_h, out_C, out_n);
}

// round 6
// speedup vs baseline: 1.0141x; 1.0141x over previous
#include <cuda_runtime.h>
#include <math.h>

#define H 4096
#define INV_SQRT_D (1.0f / 64.0f)
#define NROWS (4 * H + 2)

#define MV_BLOCKS 592          // 4 blocks/SM * 148 SMs (512 thr, 16 warps)
#define UPD_BLOCKS 1036        // 7 blocks/SM * 148 SMs (256 thr, 33KB smem)

// ---------------- device scratch (allocation-free) ----------------
__device__ float g_q[H];
__device__ float g_k[H];     // already scaled by 1/sqrt(d)
__device__ float g_v[H];
__device__ float g_opre[H];  // Wo@x + bo (pre-sigmoid)
__device__ float g_dots[2];  // wi.x, wf.x
__device__ float g_sc[3];    // i_gate, f_gate, 1/denom
__device__ int   g_ctrA;     // matvec row dispatcher (reset by gate kernel)
__device__ int   g_ctrB;     // update row dispatcher (reset by gate kernel)

// ---------------- reductions ----------------
__device__ __forceinline__ float warp_reduce(float v) {
    #pragma unroll
    for (int o = 16; o > 0; o >>= 1)
        v += __shfl_down_sync(0xffffffffu, v, o);
    return v;
}

__device__ __forceinline__ float block_reduce_1024(float v) {
    __shared__ float s[32];
    int lane = threadIdx.x & 31;
    int wid  = threadIdx.x >> 5;
    v = warp_reduce(v);
    if (lane == 0) s[wid] = v;
    __syncthreads();
    if (wid == 0) {
        v = s[lane];
        v = warp_reduce(v);
    }
    return v; // valid in warp 0
}

// ---------------- kernel A: all matvecs + scalar-gate dots ----------------
// Persistent warps; each warp steals rows from g_ctrA. Atomic latency is
// hidden by grabbing the NEXT row before streaming the current one.
__global__ void __launch_bounds__(512)
matvec_kernel(const float* __restrict__ x,
              const float* __restrict__ Wq, const float* __restrict__ Wk,
              const float* __restrict__ Wv, const float* __restrict__ Wo,
              const float* __restrict__ bq, const float* __restrict__ bk,
              const float* __restrict__ bv, const float* __restrict__ bo,
              const float* __restrict__ wi, const float* __restrict__ wf) {
    int lane = threadIdx.x & 31;
    const float4* x4 = (const float4*)x;

    int row;
    if (lane == 0) row = atomicAdd(&g_ctrA, 1);
    row = __shfl_sync(0xffffffffu, row, 0);

    while (row < NROWS) {
        int nxt = 0;
        if (lane == 0) nxt = atomicAdd(&g_ctrA, 1);   // prefetch next row id

        const float* wrow;
        if      (row <     H) wrow = Wq + (size_t) row          * H;
        else if (row < 2 * H) wrow = Wk + (size_t)(row -   H)   * H;
        else if (row < 3 * H) wrow = Wv + (size_t)(row - 2*H)   * H;
        else if (row < 4 * H) wrow = Wo + (size_t)(row - 3*H)   * H;
        else                  wrow = (row == 4 * H) ? wi : wf;

        const float4* w4 = (const float4*)wrow;

        float s0 = 0.0f, s1 = 0.0f;
        #pragma unroll 8
        for (int i = 0; i < (H / 4) / 32; i += 2) {   // 32 f4 per lane
            int ia = lane + i * 32;
            int ib = lane + (i + 1) * 32;
            float4 wa = __ldcs(&w4[ia]);
            float4 wb = __ldcs(&w4[ib]);
            float4 xa = x4[ia];
            float4 xb = x4[ib];
            s0 += wa.x * xa.x + wa.y * xa.y + wa.z * xa.z + wa.w * xa.w;
            s1 += wb.x * xb.x + wb.y * xb.y + wb.z * xb.z + wb.w * xb.w;
        }
        float sum = warp_reduce(s0 + s1);

        if (lane == 0) {
            if      (row <     H) g_q[row]          = sum + bq[row];
            else if (row < 2 * H) g_k[row -   H]    = (sum + bk[row - H]) * INV_SQRT_D;
            else if (row < 3 * H) g_v[row - 2*H]    = sum + bv[row - 2*H];
            else if (row < 4 * H) g_opre[row - 3*H] = sum + bo[row - 3*H];
            else                  g_dots[row - 4*H] = sum;
        }
        row = __shfl_sync(0xffffffffu, nxt, 0);
    }
}

// ---------------- kernel B: gates, n update, denom; resets dispatchers ----
__global__ void __launch_bounds__(1024)
gate_n_kernel(const float* __restrict__ n_prev,
              const float* __restrict__ bi, const float* __restrict__ bf,
              float* __restrict__ out_n) {
    __shared__ float s_ig, s_fg;
    int tid = threadIdx.x;
    if (tid == 0) {
        g_ctrA = 0;                       // reset matvec dispatcher for next replay
        g_ctrB = 0;                       // reset update dispatcher (consumed next)
        s_ig = expf(g_dots[0] + bi[0]);
        s_fg = 1.0f / (1.0f + expf(-(g_dots[1] + bf[0])));
    }
    __syncthreads();
    float ig = s_ig, fg = s_fg;

    float dot = 0.0f;
    #pragma unroll
    for (int i = 0; i < H / 1024; i++) {
        int j = tid + i * 1024;
        float nj = fg * n_prev[j] + ig * g_k[j];
        out_n[j] = nj;
        dot += nj * g_q[j];
    }
    dot = block_reduce_1024(dot);
    if (tid == 0) {
        float denom = fmaxf(fabsf(dot), 1.0f);
        g_sc[0] = ig;
        g_sc[1] = fg;
        g_sc[2] = 1.0f / denom;
    }
}

// ---------------- kernel C: C update + fused readout + output gate ----------
// Persistent 256-thread blocks stealing rows from g_ctrB. k,q staged to smem
// once per block (amortized over ~4 rows).
__global__ void __launch_bounds__(256)
update_kernel(const float* __restrict__ C_prev,
              float* __restrict__ out_h, float* __restrict__ out_C) {
    __shared__ float4 sk[H / 4];    // 16 KB
    __shared__ float4 sq[H / 4];    // 16 KB
    __shared__ float  red[8];
    __shared__ int    s_row;

    int tid  = threadIdx.x;
    int lane = tid & 31;
    int wid  = tid >> 5;

    // stage k, q once per block
    const float4* k4 = (const float4*)g_k;
    const float4* q4 = (const float4*)g_q;
    #pragma unroll
    for (int i = 0; i < (H / 4) / 256; i++) {
        int idx = tid + i * 256;
        sk[idx] = k4[idx];
        sq[idx] = q4[idx];
    }

    float ig = g_sc[0], fg = g_sc[1], invden = g_sc[2];

    if (tid == 0) s_row = atomicAdd(&g_ctrB, 1);
    __syncthreads();                 // staging + first row id visible
    int row = s_row;
    __syncthreads();                 // everyone copied s_row before it's rewritten

    while (row < H) {
        if (tid == 0) s_row = atomicAdd(&g_ctrB, 1);   // prefetch next row

        float ivr = ig * g_v[row];
        const float4* cp4 = (const float4*)(C_prev + (size_t)row * H);
        float4*       co4 = (float4*)      (out_C  + (size_t)row * H);

        float dot = 0.0f;
        #pragma unroll
        for (int i = 0; i < (H / 4) / 256; i++) {      // 4 iters
            int idx = tid + i * 256;
            float4 c  = __ldcs(&cp4[idx]);
            float4 kk = sk[idx];
            float4 cn;
            cn.x = fg * c.x + ivr * kk.x;
            cn.y = fg * c.y + ivr * kk.y;
            cn.z = fg * c.z + ivr * kk.z;
            cn.w = fg * c.w + ivr * kk.w;
            __stcs(&co4[idx], cn);
            float4 qq = sq[idx];
            dot += cn.x * qq.x + cn.y * qq.y + cn.z * qq.z + cn.w * qq.w;
        }

        // block reduce (result in warp 0)
        dot = warp_reduce(dot);
        if (lane == 0) red[wid] = dot;
        __syncthreads();
        if (wid == 0) {
            float t = (lane < 8) ? red[lane] : 0.0f;
            t = warp_reduce(t);
            if (lane == 0) {
                float h_tilde = t * invden;
                float o = 1.0f / (1.0f + expf(-g_opre[row]));
                out_h[row] = o * h_tilde;
            }
        }
        __syncthreads();             // red + s_row (written above) safe to read
        row = s_row;
        __syncthreads();             // all copied before next rewrite
    }
}

// ---------------- launcher ----------------
extern "C" void kernel_launch(void* const* d_in, const int* in_sizes, int n_in,
                              void* d_out, int out_size) {
    const float* x      = (const float*)d_in[0];
    // d_in[1] = h_prev (unused by mLSTM math)
    const float* C_prev = (const float*)d_in[2];
    const float* n_prev = (const float*)d_in[3];
    const float* Wq     = (const float*)d_in[4];
    const float* Wk     = (const float*)d_in[5];
    const float* Wv     = (const float*)d_in[6];
    const float* Wo     = (const float*)d_in[7];
    const float* bq     = (const float*)d_in[8];
    const float* bk     = (const float*)d_in[9];
    const float* bv     = (const float*)d_in[10];
    const float* bo     = (const float*)d_in[11];
    const float* wi     = (const float*)d_in[12];
    const float* bi     = (const float*)d_in[13];
    const float* wf     = (const float*)d_in[14];
    const float* bf     = (const float*)d_in[15];

    float* out   = (float*)d_out;
    float* out_h = out;                      // [H]
    float* out_C = out + H;                  // [H, H]
    float* out_n = out + H + (size_t)H * H;  // [H]

    matvec_kernel<<<MV_BLOCKS, 512>>>(x, Wq, Wk, Wv, Wo, bq, bk, bv, bo, wi, wf);
    gate_n_kernel<<<1, 1024>>>(n_prev, bi, bf, out_n);
    update_kernel<<<UPD_BLOCKS, 256>>>(C_prev, out_h, out_C);
}